// round 1
// baseline (speedup 1.0000x reference)
#include <cuda_runtime.h>
#include <cstdint>

// Problem constants (match reference_code)
#define B_  64
#define OH_ 120
#define OW_ 160
#define HW_ (OH_ * OW_)          // 19200
#define TOTAL_ (B_ * HW_)        // 1,228,800
#define IN_H_ 480.0f             // OH*4
#define IN_W_ 640.0f             // OW*4
#define THRESH_ 0.5f

__global__ __launch_bounds__(256)
void centerface_decode_kernel(const float* __restrict__ heatmap,   // [B,1,OH,OW]
                              const float* __restrict__ scale,     // [B,2,OH,OW]
                              const float* __restrict__ offset,    // [B,2,OH,OW]
                              const float* __restrict__ landmark,  // [B,10,OH,OW]
                              float* __restrict__ boxes,           // [B,HW,5]
                              float* __restrict__ lms,             // [B,HW,10]
                              float* __restrict__ keep)            // [B,HW]
{
    int idx = blockIdx.x * blockDim.x + threadIdx.x;
    if (idx >= TOTAL_) return;

    int b = idx / HW_;
    int p = idx - b * HW_;
    int y = p / OW_;

    // Planar, fully coalesced input loads
    float hm = heatmap[idx];                          // (B,1,H,W) linear == idx
    const float* sc = scale + (size_t)b * (2 * HW_) + p;
    float s0 = __expf(sc[0])    * 4.0f;
    float s1 = __expf(sc[HW_])  * 4.0f;
    float o0 = offset[(size_t)b * (2 * HW_) + p];     // channel 1 of offset is unused

    float y1_raw = ((float)y + o0 + 0.5f) * 4.0f - s0 * 0.5f;
    float y1c = fmaxf(y1_raw, 0.0f);
    float y1  = fminf(y1c, IN_H_);
    float x1  = fminf(y1c, IN_W_);
    float y2  = fminf(y1 + s0, IN_H_);
    float x2  = fminf(x1 + s1, IN_W_);

    float m = (hm >= THRESH_) ? 1.0f : 0.0f;          // keep mask, branch-free

    // boxes [idx][0..4] = (x1, y1, x2, y2, score) * m
    float* bo = boxes + (size_t)idx * 5;
    bo[0] = x1 * m;
    bo[1] = y1 * m;
    bo[2] = x2 * m;
    bo[3] = y2 * m;
    bo[4] = hm * m;

    // landmarks: out[2k] = lm[2k]*s0 + y1 ; out[2k+1] = lm[2k+1]*s1 + x1
    const float* lmp = landmark + (size_t)b * (10 * HW_) + p;
    float* lo = lms + (size_t)idx * 10;
#pragma unroll
    for (int j = 0; j < 10; j += 2) {
        float ly = fmaf(lmp[(size_t)j       * HW_], s0, y1);
        float lx = fmaf(lmp[(size_t)(j + 1) * HW_], s1, x1);
        lo[j]     = ly * m;
        lo[j + 1] = lx * m;
    }

    keep[idx] = m;
}

extern "C" void kernel_launch(void* const* d_in, const int* in_sizes, int n_in,
                              void* d_out, int out_size)
{
    const float* heatmap  = (const float*)d_in[0];
    const float* scale    = (const float*)d_in[1];
    const float* offset   = (const float*)d_in[2];
    const float* landmark = (const float*)d_in[3];

    float* out      = (float*)d_out;
    float* boxes    = out;                            // [B,HW,5]
    float* lms      = out + (size_t)TOTAL_ * 5;       // [B,HW,10]
    float* keep     = out + (size_t)TOTAL_ * 15;      // [B,HW]

    int threads = 256;
    int blocks = (TOTAL_ + threads - 1) / threads;    // 4800 blocks
    centerface_decode_kernel<<<blocks, threads>>>(heatmap, scale, offset, landmark,
                                                  boxes, lms, keep);
}

// round 2
// speedup vs baseline: 2.4112x; 2.4112x over previous
#include <cuda_runtime.h>
#include <cstdint>

#define B_  64
#define OH_ 120
#define OW_ 160
#define HW_ (OH_ * OW_)          // 19200
#define TOTAL_ (B_ * HW_)        // 1,228,800  (divisible by 256 -> no tail)
#define IN_H_ 480.0f
#define IN_W_ 640.0f
#define THRESH_ 0.5f

#define NTHREADS 256

__global__ __launch_bounds__(NTHREADS)
void centerface_decode_kernel(const float* __restrict__ heatmap,   // [B,1,OH,OW]
                              const float* __restrict__ scale,     // [B,2,OH,OW]
                              const float* __restrict__ offset,    // [B,2,OH,OW]
                              const float* __restrict__ landmark,  // [B,10,OH,OW]
                              float* __restrict__ boxes,           // [B,HW,5]
                              float* __restrict__ lms,             // [B,HW,10]
                              float* __restrict__ keep)            // [B,HW]
{
    __shared__ float box_s[NTHREADS * 5];    // 5 KB
    __shared__ float lm_s [NTHREADS * 10];   // 10 KB

    int tid  = threadIdx.x;
    int base = blockIdx.x * NTHREADS;        // first pixel of this block
    int idx  = base + tid;

    // TOTAL_ % 256 == 0, so no bounds check needed.
    int b = idx / HW_;
    int p = idx - b * HW_;
    int y = p / OW_;

    // ---- coalesced planar loads ----
    float hm = heatmap[idx];
    const float* sc = scale + (size_t)b * (2 * HW_) + p;
    float s0 = __expf(sc[0])   * 4.0f;
    float s1 = __expf(sc[HW_]) * 4.0f;
    float o0 = offset[(size_t)b * (2 * HW_) + p];

    float y1_raw = ((float)y + o0 + 0.5f) * 4.0f - s0 * 0.5f;
    float y1c = fmaxf(y1_raw, 0.0f);
    float y1  = fminf(y1c, IN_H_);
    float x1  = fminf(y1c, IN_W_);
    float y2  = fminf(y1 + s0, IN_H_);
    float x2  = fminf(x1 + s1, IN_W_);

    float m = (hm >= THRESH_) ? 1.0f : 0.0f;

    // ---- stage per-thread records in SMEM ----
    float* bs = box_s + tid * 5;             // stride 5: coprime with 32 banks
    bs[0] = x1 * m;
    bs[1] = y1 * m;
    bs[2] = x2 * m;
    bs[3] = y2 * m;
    bs[4] = hm * m;

    const float* lmp = landmark + (size_t)b * (10 * HW_) + p;
    float* ls = lm_s + tid * 10;
#pragma unroll
    for (int j = 0; j < 10; j += 2) {
        ls[j]     = fmaf(lmp[(size_t)j       * HW_], s0, y1) * m;
        ls[j + 1] = fmaf(lmp[(size_t)(j + 1) * HW_], s1, x1) * m;
    }

    keep[idx] = m;                           // already coalesced

    __syncthreads();

    // ---- cooperative coalesced flush: 128-bit streaming stores ----
    // boxes region for this block: 1280 contiguous floats = 320 float4 (16B-aligned:
    // base*5*4 = blockIdx*5120). landmarks: 2560 floats = 640 float4 (base*10*4 = blockIdx*10240).
    {
        const float4* src = (const float4*)box_s;
        float4*       dst = (float4*)(boxes + (size_t)base * 5);
#pragma unroll
        for (int i = 0; i < 320; i += NTHREADS) {
            int k = i + tid;
            if (k < 320) __stcs(dst + k, src[k]);
        }
    }
    {
        const float4* src = (const float4*)lm_s;
        float4*       dst = (float4*)(lms + (size_t)base * 10);
#pragma unroll
        for (int i = 0; i < 640; i += NTHREADS) {
            int k = i + tid;
            if (k < 640) __stcs(dst + k, src[k]);
        }
    }
}

extern "C" void kernel_launch(void* const* d_in, const int* in_sizes, int n_in,
                              void* d_out, int out_size)
{
    const float* heatmap  = (const float*)d_in[0];
    const float* scale    = (const float*)d_in[1];
    const float* offset   = (const float*)d_in[2];
    const float* landmark = (const float*)d_in[3];

    float* out   = (float*)d_out;
    float* boxes = out;                          // [B,HW,5]
    float* lms   = out + (size_t)TOTAL_ * 5;     // [B,HW,10]
    float* keep  = out + (size_t)TOTAL_ * 15;    // [B,HW]

    int blocks = TOTAL_ / NTHREADS;              // 4800
    centerface_decode_kernel<<<blocks, NTHREADS>>>(heatmap, scale, offset, landmark,
                                                   boxes, lms, keep);
}